// round 12
// baseline (speedup 1.0000x reference)
#include <cuda_runtime.h>
#include <cuda_bf16.h>
#include <cstdint>

// SoftThresholdAttention: B=2, N=4096, C=256, H=4, Dh=64
// d_in: 0=x, 1=q_w, 2=q_b, 3=k_w, 4=k_b, 5=v_w, 6=v_b, 7=o_w, 8=o_b, 9=tau

#define PITCH 65   // [c][d] weight tile pitch
#define QP    66   // transposed activation tile pitch (even: 8B row pairs)
#define FP    68   // attn fp32 pitch (16B-aligned rows)
#define HPW   36   // bf16 K tile pitch in u32 words (72 halves = 144B rows)

// Scratch (device globals; no allocation allowed)
__device__ float g_Q[8 * 4096 * 64];           // [b*H+h][n][d]
__device__ float g_K[8 * 4096 * 64];
__device__ float g_V[8 * 4096 * 64];
__device__ __nv_bfloat16 g_Kh[8 * 4096 * 64];  // bf16 K copy for mma filter
__device__ float g_A[8192 * 256];              // attention output, [t][c]

// ---- attn smem layout (bytes) ----------------------------------------------
#define SM_QS   0u         // 256 x FP f32   (69632)
#define SM_KS   69632u     // 128 x FP f32   (34816)
#define SM_VS   104448u    // 128 x FP f32   (34816)
#define SM_KH   139264u    // 128 x HPW u32  (18432)  bf16 K tile
#define SM_BM   157696u    // 256 rows x 4 u32 (4096)
#define SM_LS   161792u    // 16 warps x 384 int (24576)
#define SM_WL   186368u    // 16 warps x 384 f32 (24576)
#define SM_SVP  210944u    // 8 x 68 f32 (2176)
#define SM_TOTAL 213120u

// ---- helpers ----------------------------------------------------------------
__device__ __forceinline__ unsigned long long pack2(float lo, float hi) {
    unsigned long long r;
    asm("mov.b64 %0, {%1, %2};" : "=l"(r) : "f"(lo), "f"(hi));
    return r;
}
__device__ __forceinline__ void fma2acc(unsigned long long& d,
                                        unsigned long long a,
                                        unsigned long long b) {
    asm("fma.rn.f32x2 %0, %1, %2, %0;" : "+l"(d) : "l"(a), "l"(b));
}
__device__ __forceinline__ float2 unpack2(unsigned long long v) {
    float lo, hi;
    asm("mov.b64 {%0, %1}, %2;" : "=f"(lo), "=f"(hi) : "l"(v));
    return make_float2(lo, hi);
}
__device__ __forceinline__ uint32_t bf2(float lo, float hi) {
    uint32_t r;
    asm("cvt.rn.bf16x2.f32 %0, %1, %2;" : "=r"(r) : "f"(hi), "f"(lo));
    return r;
}

// ---------------------------------------------------------------------------
// QKV projection via FFMA2: out[t,c] = sum_d x[t,d]*W[c,d] + b[c].
// ---------------------------------------------------------------------------
__global__ __launch_bounds__(256) void qkv_kernel(
    const float* __restrict__ x,
    const float* __restrict__ qw, const float* __restrict__ qb,
    const float* __restrict__ kw, const float* __restrict__ kb,
    const float* __restrict__ vw, const float* __restrict__ vb)
{
    __shared__ float AsT[64 * QP];     // [d][r]
    __shared__ float Ws[64 * PITCH];   // [c][d]

    const int z = blockIdx.z;
    const float* __restrict__ W    = (z == 0) ? qw : (z == 1) ? kw : vw;
    const float* __restrict__ bias = (z == 0) ? qb : (z == 1) ? kb : vb;
    float* __restrict__ dst        = (z == 0) ? g_Q : (z == 1) ? g_K : g_V;

    const int tr = blockIdx.x * 64;
    const int tc = blockIdx.y * 64;
    const int tid  = threadIdx.x;
    const int warp = tid >> 5;
    const int lane = tid & 31;

    unsigned long long acc2[4][2];
    #pragma unroll
    for (int p = 0; p < 4; p++) { acc2[p][0] = 0ull; acc2[p][1] = 0ull; }

    for (int kb_ = 0; kb_ < 256; kb_ += 64) {
        const float4* X4 = (const float4*)(x + tr * 256 + kb_);
        const float4* W4 = (const float4*)(W + tc * 256 + kb_);
        #pragma unroll
        for (int it = 0; it < 4; it++) {
            int idx = tid + it * 256;      // < 1024
            int r = idx >> 4, d4 = idx & 15;
            float4 v = X4[r * 64 + d4];
            AsT[(d4 * 4 + 0) * QP + r] = v.x;
            AsT[(d4 * 4 + 1) * QP + r] = v.y;
            AsT[(d4 * 4 + 2) * QP + r] = v.z;
            AsT[(d4 * 4 + 3) * QP + r] = v.w;
            float4 wv = W4[r * 64 + d4];
            float* p = &Ws[r * PITCH + d4 * 4];
            p[0] = wv.x; p[1] = wv.y; p[2] = wv.z; p[3] = wv.w;
        }
        __syncthreads();

        #pragma unroll 8
        for (int d = 0; d < 64; d++) {
            const float* arow = &AsT[d * QP + warp * 8];
            unsigned long long ra[4];
            #pragma unroll
            for (int p = 0; p < 4; p++)
                ra[p] = *(const unsigned long long*)(arow + 2 * p);
            unsigned long long bb[2];
            #pragma unroll
            for (int jc = 0; jc < 2; jc++) {
                float b = Ws[(lane + 32 * jc) * PITCH + d];
                bb[jc] = pack2(b, b);
            }
            #pragma unroll
            for (int p = 0; p < 4; p++) {
                fma2acc(acc2[p][0], ra[p], bb[0]);
                fma2acc(acc2[p][1], ra[p], bb[1]);
            }
        }
        __syncthreads();
    }

    #pragma unroll
    for (int p = 0; p < 4; p++) {
        #pragma unroll
        for (int jc = 0; jc < 2; jc++) {
            float2 v = unpack2(acc2[p][jc]);
            int c = tc + lane + 32 * jc;
            int h = c >> 6, dd = c & 63;
            float bv = bias[c];
            int t0 = tr + warp * 8 + 2 * p;
            int b0 = t0 >> 12, n0 = t0 & 4095;
            dst[((b0 * 4 + h) * 4096 + n0) * 64 + dd] = v.x + bv;
            int t1 = t0 + 1;
            int b1 = t1 >> 12, n1 = t1 & 4095;
            dst[((b1 * 4 + h) * 4096 + n1) * 64 + dd] = v.y + bv;
        }
    }
}

// ---------------------------------------------------------------------------
// K fp32 -> bf16 conversion (coalesced, bandwidth-bound, ~3us).
// ---------------------------------------------------------------------------
__global__ __launch_bounds__(512) void cvtk_kernel()
{
    int i = blockIdx.x * 512 + threadIdx.x;   // over float2 granules
    const float2* src = (const float2*)g_K;
    uint32_t* dst = (uint32_t*)g_Kh;
    float2 v = src[i];
    dst[i] = bf2(v.x, v.y);
}

// ---------------------------------------------------------------------------
// Attention: bf16 mma.sync filter + exact fp32 recompute of candidates.
// R7 candidate structure (4 groups of 4 rows, simple exact pass) + hoisted
// bf16 cvt. grid (16 q-tiles of 256 rows, 8 bh), block 512 = 16 warps; warp
// owns 16 rows, O in registers. Exact dot: sequential accumulator.
// denom = 4096 + sum(e^v - 1 over v>tau); O = (sumV + sum w*V) / denom.
// ---------------------------------------------------------------------------
__global__ __launch_bounds__(512, 1) void attn_kernel(const float* __restrict__ tau_p)
{
    extern __shared__ char smem[];
    float*    Qs   = (float*)(smem + SM_QS);
    float*    Ks   = (float*)(smem + SM_KS);
    float*    Vs   = (float*)(smem + SM_VS);
    uint32_t* Kh32 = (uint32_t*)(smem + SM_KH);
    uint32_t* Bm   = (uint32_t*)(smem + SM_BM);
    int*      Ls   = (int*)(smem + SM_LS);
    float*    Wl   = (float*)(smem + SM_WL);
    float*    SVp  = (float*)(smem + SM_SVP);

    const int qt = blockIdx.x, bh = blockIdx.y;
    const int tid  = threadIdx.x;
    const int warp = tid >> 5;
    const int lane = tid & 31;
    const int gid  = lane >> 2;      // mma group id (0..7)
    const int tg   = lane & 3;       // thread in group
    const int R0   = warp * 16;      // warp-owned rows [R0, R0+16)
    const float tau   = tau_p[0];
    const float scale = 0.0625f;                 // 256^-0.5
    const float thrA  = (tau - 0.03f) * 16.0f;   // raw-S filter threshold

    const float* __restrict__ Qg = g_Q + (bh * 4096 + qt * 256) * 64;
    const float* __restrict__ Kg = g_K + bh * 4096 * 64;
    const float* __restrict__ Vg = g_V + bh * 4096 * 64;
    const __nv_bfloat16* __restrict__ Khg = g_Kh + bh * 4096 * 64;

    // load Q tile (256 x 64) fp32
    {
        const float4* Q4 = (const float4*)Qg;
        #pragma unroll
        for (int it = 0; it < 8; it++) {
            int idx = tid + it * 512;      // < 4096
            int r = idx >> 4, d = (idx & 15) * 4;
            *(float4*)&Qs[r * FP + d] = Q4[idx];
        }
    }
    __syncthreads();

    // A fragments (warp's 16 rows) converted fp32->bf16 from Qs.
    uint32_t afr[4][4];
    #pragma unroll
    for (int ks = 0; ks < 4; ks++) {
        int c0 = ks * 16 + 2 * tg;
        float2 q00 = *(const float2*)&Qs[(R0 + gid) * FP + c0];
        float2 q10 = *(const float2*)&Qs[(R0 + gid + 8) * FP + c0];
        float2 q01 = *(const float2*)&Qs[(R0 + gid) * FP + c0 + 8];
        float2 q11 = *(const float2*)&Qs[(R0 + gid + 8) * FP + c0 + 8];
        afr[ks][0] = bf2(q00.x, q00.y);
        afr[ks][1] = bf2(q10.x, q10.y);
        afr[ks][2] = bf2(q01.x, q01.y);
        afr[ks][3] = bf2(q11.x, q11.y);
    }

    float O[16][2] = {};
    float dl[16]   = {};
    float sv = 0.0f;
    const int svg = tid >> 6, svd = tid & 63;   // 8 groups x 16 keys
    const int wb = warp * 384;

    for (int kt = 0; kt < 32; kt++) {
        __syncthreads();   // prior tile readers done

        // ---- load K fp32 / V fp32 / Kh bf16 tiles (independent streams) ----
        {
            const float4* K4 = (const float4*)(Kg + kt * 128 * 64);
            const float4* V4 = (const float4*)(Vg + kt * 128 * 64);
            const uint2*  H2 = (const uint2*)(Khg + kt * 128 * 64);
            #pragma unroll
            for (int it = 0; it < 4; it++) {
                int idx = tid + it * 512;      // < 2048
                int r = idx >> 4, d = (idx & 15) * 4;
                *(float4*)&Ks[r * FP + d] = K4[idx];
                *(float4*)&Vs[r * FP + d] = V4[idx];
                *(uint2*)&Kh32[r * HPW + (d >> 1)] = H2[idx];
            }
        }
        __syncthreads();

        // ---- sumV partial ---------------------------------------------------
        #pragma unroll 8
        for (int k = 0; k < 16; k++)
            sv += Vs[(svg * 16 + k) * FP + svd];

        // ---- approx scores via mma.sync; bitmap for warp's 16 rows ---------
        {
            uint32_t wacc = 0;
            #pragma unroll
            for (int nb = 0; nb < 16; nb++) {
                float d0 = 0.0f, d1 = 0.0f, d2 = 0.0f, d3 = 0.0f;
                #pragma unroll
                for (int ks = 0; ks < 4; ks++) {
                    int kr = nb * 8 + gid;            // key (B col n)
                    uint32_t b0 = Kh32[kr * HPW + ks * 8 + tg];
                    uint32_t b1 = Kh32[kr * HPW + ks * 8 + tg + 4];
                    asm volatile(
                        "mma.sync.aligned.m16n8k16.row.col.f32.bf16.bf16.f32 "
                        "{%0,%1,%2,%3}, {%4,%5,%6,%7}, {%8,%9}, {%0,%1,%2,%3};"
                        : "+f"(d0), "+f"(d1), "+f"(d2), "+f"(d3)
                        : "r"(afr[ks][0]), "r"(afr[ks][1]),
                          "r"(afr[ks][2]), "r"(afr[ks][3]),
                          "r"(b0), "r"(b1));
                }
                // d0:(gid,2tg) d1:(gid,2tg+1) d2:(gid+8,2tg) d3:(gid+8,2tg+1)
                unsigned B0 = __ballot_sync(0xffffffffu, d0 > thrA);
                unsigned B1 = __ballot_sync(0xffffffffu, d1 > thrA);
                unsigned B2 = __ballot_sync(0xffffffffu, d2 > thrA);
                unsigned B3 = __ballot_sync(0xffffffffu, d3 > thrA);
                if (lane < 16) {
                    int row = lane;
                    unsigned ne, no;
                    if (row < 8) { ne = (B0 >> (row * 4)) & 0xF; no = (B1 >> (row * 4)) & 0xF; }
                    else         { ne = (B2 >> ((row - 8) * 4)) & 0xF; no = (B3 >> ((row - 8) * 4)) & 0xF; }
                    unsigned byte =  (ne & 1u)        | ((no & 1u) << 1)
                                  | ((ne & 2u) << 1)  | ((no & 2u) << 2)
                                  | ((ne & 4u) << 2)  | ((no & 4u) << 3)
                                  | ((ne & 8u) << 3)  | ((no & 8u) << 4);
                    wacc |= byte << ((nb & 3) * 8);
                    if ((nb & 3) == 3) {
                        Bm[(R0 + row) * 4 + (nb >> 2)] = wacc;
                        wacc = 0;
                    }
                }
            }
        }
        __syncwarp();

        // ---- candidate passes: 4 groups of 4 rows (R7 structure) -----------
        #pragma unroll
        for (int g = 0; g < 4; g++) {
            // lane < 16 owns (rowL = g*4 + lane>>2, word = lane&3)
            uint32_t m = 0;
            int cnt = 0;
            int rowL = g * 4 + (lane >> 2);
            if (lane < 16) {
                m = Bm[(R0 + rowL) * 4 + (lane & 3)];
                cnt = __popc(m);
            }
            int pre = cnt;
            #pragma unroll
            for (int off = 1; off < 16; off <<= 1) {
                int n = __shfl_up_sync(0xffffffffu, pre, off);
                if (lane >= off && lane < 16) pre += n;
            }
            int base = pre - cnt;
            int total = __shfl_sync(0xffffffffu, pre, 15);
            {
                int i = 0;
                while (m) {
                    int c = __ffs(m) - 1;
                    m &= m - 1;
                    Ls[wb + base + i] = (rowL << 16) | ((lane & 3) * 32 + c);
                    i++;
                }
            }
            __syncwarp();

            // exact fp32 recompute: SEQUENTIAL single accumulator over d
            for (int cb = 0; cb < total; cb += 32) {
                int ci = cb + lane;
                float w = 0.0f;
                if (ci < total) {
                    int e = Ls[wb + ci];
                    int rl = e >> 16, c = e & 0xFFFF;
                    const float4* qr = (const float4*)&Qs[(R0 + rl) * FP];
                    const float4* kc = (const float4*)&Ks[c * FP];
                    float acc = 0.0f;
                    #pragma unroll
                    for (int d = 0; d < 16; d++) {
                        float4 qv = qr[d], kv = kc[d];
                        acc = fmaf(qv.x, kv.x, acc);
                        acc = fmaf(qv.y, kv.y, acc);
                        acc = fmaf(qv.z, kv.z, acc);
                        acc = fmaf(qv.w, kv.w, acc);
                    }
                    float v = acc * scale;
                    if (v > tau) w = __expf(v) - 1.0f;
                }
                if (ci < total) Wl[wb + ci] = w;
            }
            __syncwarp();

            // scatter: list is row-grouped, so O index is compile-time
            #pragma unroll
            for (int j = 0; j < 4; j++) {
                int startj = (j == 0) ? 0 : __shfl_sync(0xffffffffu, pre, j * 4 - 1);
                int endj   = __shfl_sync(0xffffffffu, pre, j * 4 + 3);
                for (int t = startj; t < endj; t++) {
                    float w = Wl[wb + t];               // broadcast
                    int   c = Ls[wb + t] & 0xFFFF;      // broadcast
                    O[g * 4 + j][0] += w * Vs[c * FP + lane];
                    O[g * 4 + j][1] += w * Vs[c * FP + lane + 32];
                    dl[g * 4 + j] += w;
                }
            }
            __syncwarp();
        }
    }

    // ---- combine sumV partials --------------------------------------------
    __syncthreads();
    SVp[svg * 68 + svd] = sv;
    __syncthreads();
    float sv0 = 0.0f, sv1 = 0.0f;
    #pragma unroll
    for (int gg = 0; gg < 8; gg++) {
        sv0 += SVp[gg * 68 + lane];
        sv1 += SVp[gg * 68 + lane + 32];
    }

    // ---- finalize: rows owned by this warp --------------------------------
    const int b_ = bh >> 2, h = bh & 3;
    const int tbase = b_ * 4096 + qt * 256;
    #pragma unroll
    for (int i = 0; i < 16; i++) {
        float inv = 1.0f / (4096.0f + dl[i]);
        int t = tbase + R0 + i;
        g_A[t * 256 + h * 64 + lane]      = (sv0 + O[i][0]) * inv;
        g_A[t * 256 + h * 64 + lane + 32] = (sv1 + O[i][1]) * inv;
    }
}

// ---------------------------------------------------------------------------
// Output projection via FFMA2: out[t,c] = sum_d g_A[t,d]*o_w[c,d] + o_b[c]
// ---------------------------------------------------------------------------
__global__ __launch_bounds__(256) void oproj_kernel(
    const float* __restrict__ ow, const float* __restrict__ ob,
    float* __restrict__ out)
{
    __shared__ float AsT[64 * QP];     // [d][r]
    __shared__ float Ws[64 * PITCH];   // [c][d]

    const int tr = blockIdx.x * 64;
    const int tc = blockIdx.y * 64;
    const int tid  = threadIdx.x;
    const int warp = tid >> 5;
    const int lane = tid & 31;

    unsigned long long acc2[4][2];
    #pragma unroll
    for (int p = 0; p < 4; p++) { acc2[p][0] = 0ull; acc2[p][1] = 0ull; }

    for (int kb_ = 0; kb_ < 256; kb_ += 64) {
        const float4* X4 = (const float4*)(g_A + tr * 256 + kb_);
        const float4* W4 = (const float4*)(ow + tc * 256 + kb_);
        #pragma unroll
        for (int it = 0; it < 4; it++) {
            int idx = tid + it * 256;      // < 1024
            int r = idx >> 4, d4 = idx & 15;
            float4 v = X4[r * 64 + d4];
            AsT[(d4 * 4 + 0) * QP + r] = v.x;
            AsT[(d4 * 4 + 1) * QP + r] = v.y;
            AsT[(d4 * 4 + 2) * QP + r] = v.z;
            AsT[(d4 * 4 + 3) * QP + r] = v.w;
            float4 wv = W4[r * 64 + d4];
            float* p = &Ws[r * PITCH + d4 * 4];
            p[0] = wv.x; p[1] = wv.y; p[2] = wv.z; p[3] = wv.w;
        }
        __syncthreads();

        #pragma unroll 8
        for (int d = 0; d < 64; d++) {
            const float* arow = &AsT[d * QP + warp * 8];
            unsigned long long ra[4];
            #pragma unroll
            for (int p = 0; p < 4; p++)
                ra[p] = *(const unsigned long long*)(arow + 2 * p);
            unsigned long long bb[2];
            #pragma unroll
            for (int jc = 0; jc < 2; jc++) {
                float b = Ws[(lane + 32 * jc) * PITCH + d];
                bb[jc] = pack2(b, b);
            }
            #pragma unroll
            for (int p = 0; p < 4; p++) {
                fma2acc(acc2[p][0], ra[p], bb[0]);
                fma2acc(acc2[p][1], ra[p], bb[1]);
            }
        }
        __syncthreads();
    }

    #pragma unroll
    for (int p = 0; p < 4; p++) {
        #pragma unroll
        for (int jc = 0; jc < 2; jc++) {
            float2 v = unpack2(acc2[p][jc]);
            int c = tc + lane + 32 * jc;
            float bv = ob[c];
            int t0 = tr + warp * 8 + 2 * p;
            out[t0 * 256 + c]       = v.x + bv;
            out[(t0 + 1) * 256 + c] = v.y + bv;
        }
    }
}

// ---------------------------------------------------------------------------
extern "C" void kernel_launch(void* const* d_in, const int* in_sizes, int n_in,
                              void* d_out, int out_size)
{
    const float* x   = (const float*)d_in[0];
    const float* qw  = (const float*)d_in[1];
    const float* qb  = (const float*)d_in[2];
    const float* kw  = (const float*)d_in[3];
    const float* kb  = (const float*)d_in[4];
    const float* vw  = (const float*)d_in[5];
    const float* vb  = (const float*)d_in[6];
    const float* ow  = (const float*)d_in[7];
    const float* ob  = (const float*)d_in[8];
    const float* tau = (const float*)d_in[9];
    float* out = (float*)d_out;

    // QKV projections (FFMA2)
    dim3 gq(128, 4, 3);
    qkv_kernel<<<gq, 256>>>(x, qw, qb, kw, kb, vw, vb);

    // K -> bf16 copy (coalesced)
    cvtk_kernel<<<(8 * 4096 * 64 / 2) / 512, 512>>>();

    // attention: HMMA filter + exact sparse recompute
    static bool attr_set = false;
    if (!attr_set) {
        cudaFuncSetAttribute(attn_kernel,
                             cudaFuncAttributeMaxDynamicSharedMemorySize,
                             SM_TOTAL);
        attr_set = true;
    }
    dim3 ga(16, 8);
    attn_kernel<<<ga, 512, SM_TOTAL>>>(tau);

    // output projection (FFMA2)
    dim3 go(128, 4);
    oproj_kernel<<<go, 256>>>(ow, ob, out);
}

// round 15
// speedup vs baseline: 1.0077x; 1.0077x over previous
#include <cuda_runtime.h>
#include <cuda_bf16.h>
#include <cstdint>

// SoftThresholdAttention: B=2, N=4096, C=256, H=4, Dh=64
// d_in: 0=x, 1=q_w, 2=q_b, 3=k_w, 4=k_b, 5=v_w, 6=v_b, 7=o_w, 8=o_b, 9=tau

#define PITCH 65   // [c][d] weight tile pitch
#define QP    66   // oproj transposed activation pitch
#define QP2   130  // qkv transposed activation pitch (128 rows + 2, even)
#define FP    68   // attn fp32 pitch (16B-aligned rows)
#define HPW   36   // bf16 K tile pitch in u32 words (72 halves = 144B rows)

// Scratch (device globals; no allocation allowed)
__device__ float g_Q[8 * 4096 * 64];           // [b*H+h][n][d]
__device__ float g_K[8 * 4096 * 64];
__device__ float g_V[8 * 4096 * 64];
__device__ __nv_bfloat16 g_Kh[8 * 4096 * 64];  // bf16 K copy for mma filter
__device__ float g_A[8192 * 256];              // attention output, [t][c]

// ---- attn smem layout (bytes) ----------------------------------------------
#define SM_QS   0u         // 256 x FP f32   (69632)
#define SM_KS   69632u     // 128 x FP f32   (34816)
#define SM_VS   104448u    // 128 x FP f32   (34816)
#define SM_KH   139264u    // 128 x HPW u32  (18432)  bf16 K tile
#define SM_BM   157696u    // 256 rows x 4 u32 (4096)
#define SM_LS   161792u    // 16 warps x 384 int (24576)
#define SM_WL   186368u    // 16 warps x 384 f32 (24576)
#define SM_SVP  210944u    // 8 x 68 f32 (2176)
#define SM_TOTAL 213120u

// ---- helpers ----------------------------------------------------------------
__device__ __forceinline__ unsigned long long pack2(float lo, float hi) {
    unsigned long long r;
    asm("mov.b64 %0, {%1, %2};" : "=l"(r) : "f"(lo), "f"(hi));
    return r;
}
__device__ __forceinline__ void fma2acc(unsigned long long& d,
                                        unsigned long long a,
                                        unsigned long long b) {
    asm("fma.rn.f32x2 %0, %1, %2, %0;" : "+l"(d) : "l"(a), "l"(b));
}
__device__ __forceinline__ float2 unpack2(unsigned long long v) {
    float lo, hi;
    asm("mov.b64 {%0, %1}, %2;" : "=f"(lo), "=f"(hi) : "l"(v));
    return make_float2(lo, hi);
}
__device__ __forceinline__ uint32_t bf2(float lo, float hi) {
    uint32_t r;
    asm("cvt.rn.bf16x2.f32 %0, %1, %2;" : "=r"(r) : "f"(hi), "f"(lo));
    return r;
}

// ---------------------------------------------------------------------------
// QKV projection via FFMA2, 128x64 tiles: out[t,c] = sum_d x[t,d]*W[c,d]+b[c]
// grid (64, 4, 3), block 256 = 8 warps; warp owns 16 rows (8 pairs).
// x tile stored transposed (AsT[d][r]) so row pairs load as one LDS.64.
// Per-output accumulation order identical to the 64-row version.
// ---------------------------------------------------------------------------
__global__ __launch_bounds__(256) void qkv_kernel(
    const float* __restrict__ x,
    const float* __restrict__ qw, const float* __restrict__ qb,
    const float* __restrict__ kw, const float* __restrict__ kb,
    const float* __restrict__ vw, const float* __restrict__ vb)
{
    extern __shared__ float qsm[];
    float* AsT = qsm;                  // [d][r] 64 x QP2
    float* Ws  = qsm + 64 * QP2;       // [c][d] 64 x PITCH

    const int z = blockIdx.z;
    const float* __restrict__ W    = (z == 0) ? qw : (z == 1) ? kw : vw;
    const float* __restrict__ bias = (z == 0) ? qb : (z == 1) ? kb : vb;
    float* __restrict__ dst        = (z == 0) ? g_Q : (z == 1) ? g_K : g_V;

    const int tr = blockIdx.x * 128;
    const int tc = blockIdx.y * 64;
    const int tid  = threadIdx.x;
    const int warp = tid >> 5;
    const int lane = tid & 31;

    unsigned long long acc2[8][2];
    #pragma unroll
    for (int p = 0; p < 8; p++) { acc2[p][0] = 0ull; acc2[p][1] = 0ull; }

    for (int kb_ = 0; kb_ < 256; kb_ += 64) {
        const float4* X4 = (const float4*)(x + tr * 256 + kb_);
        const float4* W4 = (const float4*)(W + tc * 256 + kb_);
        #pragma unroll
        for (int it = 0; it < 8; it++) {
            int idx = tid + it * 256;      // < 2048
            int r = idx >> 4, d4 = idx & 15;
            float4 v = X4[r * 64 + d4];
            AsT[(d4 * 4 + 0) * QP2 + r] = v.x;
            AsT[(d4 * 4 + 1) * QP2 + r] = v.y;
            AsT[(d4 * 4 + 2) * QP2 + r] = v.z;
            AsT[(d4 * 4 + 3) * QP2 + r] = v.w;
        }
        #pragma unroll
        for (int it = 0; it < 4; it++) {
            int idx = tid + it * 256;      // < 1024
            int r = idx >> 4, d4 = idx & 15;
            float4 wv = W4[r * 64 + d4];
            float* p = &Ws[r * PITCH + d4 * 4];
            p[0] = wv.x; p[1] = wv.y; p[2] = wv.z; p[3] = wv.w;
        }
        __syncthreads();

        #pragma unroll 4
        for (int d = 0; d < 64; d++) {
            const float* arow = &AsT[d * QP2 + warp * 16];
            unsigned long long ra[8];
            #pragma unroll
            for (int p = 0; p < 8; p++)
                ra[p] = *(const unsigned long long*)(arow + 2 * p);
            unsigned long long bb[2];
            #pragma unroll
            for (int jc = 0; jc < 2; jc++) {
                float b = Ws[(lane + 32 * jc) * PITCH + d];
                bb[jc] = pack2(b, b);
            }
            #pragma unroll
            for (int p = 0; p < 8; p++) {
                fma2acc(acc2[p][0], ra[p], bb[0]);
                fma2acc(acc2[p][1], ra[p], bb[1]);
            }
        }
        __syncthreads();
    }

    #pragma unroll
    for (int p = 0; p < 8; p++) {
        #pragma unroll
        for (int jc = 0; jc < 2; jc++) {
            float2 v = unpack2(acc2[p][jc]);
            int c = tc + lane + 32 * jc;
            int h = c >> 6, dd = c & 63;
            float bv = bias[c];
            int t0 = tr + warp * 16 + 2 * p;
            int b0 = t0 >> 12, n0 = t0 & 4095;
            dst[((b0 * 4 + h) * 4096 + n0) * 64 + dd] = v.x + bv;
            int t1 = t0 + 1;
            int b1 = t1 >> 12, n1 = t1 & 4095;
            dst[((b1 * 4 + h) * 4096 + n1) * 64 + dd] = v.y + bv;
        }
    }
}

// ---------------------------------------------------------------------------
// K fp32 -> bf16 conversion (coalesced, bandwidth-bound, ~3us).
// ---------------------------------------------------------------------------
__global__ __launch_bounds__(512) void cvtk_kernel()
{
    int i = blockIdx.x * 512 + threadIdx.x;   // over float2 granules
    const float2* src = (const float2*)g_K;
    uint32_t* dst = (uint32_t*)g_Kh;
    float2 v = src[i];
    dst[i] = bf2(v.x, v.y);
}

// ---------------------------------------------------------------------------
// Attention: bf16 mma.sync filter + exact fp32 recompute of candidates.
// (R11 kernel, verbatim.) grid (16 q-tiles of 256 rows, 8 bh), block 512 =
// 16 warps; warp owns 16 rows, O in registers. Exact dot: sequential
// accumulator (gate-stable).
// denom = 4096 + sum(e^v - 1 over v>tau); O = (sumV + sum w*V) / denom.
// ---------------------------------------------------------------------------
__global__ __launch_bounds__(512, 1) void attn_kernel(const float* __restrict__ tau_p)
{
    extern __shared__ char smem[];
    float*    Qs   = (float*)(smem + SM_QS);
    float*    Ks   = (float*)(smem + SM_KS);
    float*    Vs   = (float*)(smem + SM_VS);
    uint32_t* Kh32 = (uint32_t*)(smem + SM_KH);
    uint32_t* Bm   = (uint32_t*)(smem + SM_BM);
    int*      Ls   = (int*)(smem + SM_LS);
    float*    Wl   = (float*)(smem + SM_WL);
    float*    SVp  = (float*)(smem + SM_SVP);

    const int qt = blockIdx.x, bh = blockIdx.y;
    const int tid  = threadIdx.x;
    const int warp = tid >> 5;
    const int lane = tid & 31;
    const int gid  = lane >> 2;      // mma group id (0..7)
    const int tg   = lane & 3;       // thread in group
    const int R0   = warp * 16;      // warp-owned rows [R0, R0+16)
    const float tau   = tau_p[0];
    const float scale = 0.0625f;                 // 256^-0.5
    const float thrA  = (tau - 0.03f) * 16.0f;   // raw-S filter threshold

    const float* __restrict__ Qg = g_Q + (bh * 4096 + qt * 256) * 64;
    const float* __restrict__ Kg = g_K + bh * 4096 * 64;
    const float* __restrict__ Vg = g_V + bh * 4096 * 64;
    const __nv_bfloat16* __restrict__ Khg = g_Kh + bh * 4096 * 64;

    // load Q tile (256 x 64) fp32
    {
        const float4* Q4 = (const float4*)Qg;
        #pragma unroll
        for (int it = 0; it < 8; it++) {
            int idx = tid + it * 512;      // < 4096
            int r = idx >> 4, d = (idx & 15) * 4;
            *(float4*)&Qs[r * FP + d] = Q4[idx];
        }
    }
    __syncthreads();

    // A fragments (warp's 16 rows) converted fp32->bf16 from Qs.
    uint32_t afr[4][4];
    #pragma unroll
    for (int ks = 0; ks < 4; ks++) {
        int c0 = ks * 16 + 2 * tg;
        float2 q00 = *(const float2*)&Qs[(R0 + gid) * FP + c0];
        float2 q10 = *(const float2*)&Qs[(R0 + gid + 8) * FP + c0];
        float2 q01 = *(const float2*)&Qs[(R0 + gid) * FP + c0 + 8];
        float2 q11 = *(const float2*)&Qs[(R0 + gid + 8) * FP + c0 + 8];
        afr[ks][0] = bf2(q00.x, q00.y);
        afr[ks][1] = bf2(q10.x, q10.y);
        afr[ks][2] = bf2(q01.x, q01.y);
        afr[ks][3] = bf2(q11.x, q11.y);
    }

    float O[16][2] = {};
    float dl[16]   = {};
    float sv = 0.0f;
    const int svg = tid >> 6, svd = tid & 63;   // 8 groups x 16 keys
    const int wb = warp * 384;

    for (int kt = 0; kt < 32; kt++) {
        __syncthreads();   // prior tile readers done

        // ---- load K fp32 / V fp32 / Kh bf16 tiles (independent streams) ----
        {
            const float4* K4 = (const float4*)(Kg + kt * 128 * 64);
            const float4* V4 = (const float4*)(Vg + kt * 128 * 64);
            const uint2*  H2 = (const uint2*)(Khg + kt * 128 * 64);
            #pragma unroll
            for (int it = 0; it < 4; it++) {
                int idx = tid + it * 512;      // < 2048
                int r = idx >> 4, d = (idx & 15) * 4;
                *(float4*)&Ks[r * FP + d] = K4[idx];
                *(float4*)&Vs[r * FP + d] = V4[idx];
                *(uint2*)&Kh32[r * HPW + (d >> 1)] = H2[idx];
            }
        }
        __syncthreads();

        // ---- sumV partial ---------------------------------------------------
        #pragma unroll 8
        for (int k = 0; k < 16; k++)
            sv += Vs[(svg * 16 + k) * FP + svd];

        // ---- approx scores via mma.sync; bitmap for warp's 16 rows ---------
        {
            uint32_t wacc = 0;
            #pragma unroll
            for (int nb = 0; nb < 16; nb++) {
                float d0 = 0.0f, d1 = 0.0f, d2 = 0.0f, d3 = 0.0f;
                #pragma unroll
                for (int ks = 0; ks < 4; ks++) {
                    int kr = nb * 8 + gid;            // key (B col n)
                    uint32_t b0 = Kh32[kr * HPW + ks * 8 + tg];
                    uint32_t b1 = Kh32[kr * HPW + ks * 8 + tg + 4];
                    asm volatile(
                        "mma.sync.aligned.m16n8k16.row.col.f32.bf16.bf16.f32 "
                        "{%0,%1,%2,%3}, {%4,%5,%6,%7}, {%8,%9}, {%0,%1,%2,%3};"
                        : "+f"(d0), "+f"(d1), "+f"(d2), "+f"(d3)
                        : "r"(afr[ks][0]), "r"(afr[ks][1]),
                          "r"(afr[ks][2]), "r"(afr[ks][3]),
                          "r"(b0), "r"(b1));
                }
                // d0:(gid,2tg) d1:(gid,2tg+1) d2:(gid+8,2tg) d3:(gid+8,2tg+1)
                unsigned B0 = __ballot_sync(0xffffffffu, d0 > thrA);
                unsigned B1 = __ballot_sync(0xffffffffu, d1 > thrA);
                unsigned B2 = __ballot_sync(0xffffffffu, d2 > thrA);
                unsigned B3 = __ballot_sync(0xffffffffu, d3 > thrA);
                if (lane < 16) {
                    int row = lane;
                    unsigned ne, no;
                    if (row < 8) { ne = (B0 >> (row * 4)) & 0xF; no = (B1 >> (row * 4)) & 0xF; }
                    else         { ne = (B2 >> ((row - 8) * 4)) & 0xF; no = (B3 >> ((row - 8) * 4)) & 0xF; }
                    unsigned byte =  (ne & 1u)        | ((no & 1u) << 1)
                                  | ((ne & 2u) << 1)  | ((no & 2u) << 2)
                                  | ((ne & 4u) << 2)  | ((no & 4u) << 3)
                                  | ((ne & 8u) << 3)  | ((no & 8u) << 4);
                    wacc |= byte << ((nb & 3) * 8);
                    if ((nb & 3) == 3) {
                        Bm[(R0 + row) * 4 + (nb >> 2)] = wacc;
                        wacc = 0;
                    }
                }
            }
        }
        __syncwarp();

        // ---- candidate passes: 2 groups of 8 rows --------------------------
        #pragma unroll
        for (int g = 0; g < 2; g++) {
            int rowL = g * 8 + (lane >> 2);
            uint32_t m = Bm[(R0 + rowL) * 4 + (lane & 3)];
            int cnt = __popc(m);
            int pre = cnt;
            #pragma unroll
            for (int off = 1; off < 32; off <<= 1) {
                int n = __shfl_up_sync(0xffffffffu, pre, off);
                if (lane >= off) pre += n;
            }
            int base = pre - cnt;
            int total = __shfl_sync(0xffffffffu, pre, 31);
            {
                int i = 0;
                while (m) {
                    int c = __ffs(m) - 1;
                    m &= m - 1;
                    Ls[wb + base + i] = (rowL << 16) | ((lane & 3) * 32 + c);
                    i++;
                }
            }
            __syncwarp();

            // exact fp32 recompute: SEQUENTIAL accumulator per candidate,
            // ILP-2 across two 32-candidate batches.
            for (int cb = 0; cb < total; cb += 64) {
                int ci0 = cb + lane, ci1 = cb + 32 + lane;
                bool v0ok = ci0 < total, v1ok = ci1 < total;
                int e0 = v0ok ? Ls[wb + ci0] : 0;
                int e1 = v1ok ? Ls[wb + ci1] : 0;
                const float4* qr0 = (const float4*)&Qs[(R0 + (e0 >> 16)) * FP];
                const float4* kc0 = (const float4*)&Ks[(e0 & 0xFFFF) * FP];
                const float4* qr1 = (const float4*)&Qs[(R0 + (e1 >> 16)) * FP];
                const float4* kc1 = (const float4*)&Ks[(e1 & 0xFFFF) * FP];
                float acc0 = 0.0f, acc1 = 0.0f;
                if (v1ok) {
                    #pragma unroll
                    for (int d = 0; d < 16; d++) {
                        float4 q0 = qr0[d], k0 = kc0[d];
                        float4 q1 = qr1[d], k1 = kc1[d];
                        acc0 = fmaf(q0.x, k0.x, acc0);
                        acc1 = fmaf(q1.x, k1.x, acc1);
                        acc0 = fmaf(q0.y, k0.y, acc0);
                        acc1 = fmaf(q1.y, k1.y, acc1);
                        acc0 = fmaf(q0.z, k0.z, acc0);
                        acc1 = fmaf(q1.z, k1.z, acc1);
                        acc0 = fmaf(q0.w, k0.w, acc0);
                        acc1 = fmaf(q1.w, k1.w, acc1);
                    }
                } else if (v0ok) {
                    #pragma unroll
                    for (int d = 0; d < 16; d++) {
                        float4 q0 = qr0[d], k0 = kc0[d];
                        acc0 = fmaf(q0.x, k0.x, acc0);
                        acc0 = fmaf(q0.y, k0.y, acc0);
                        acc0 = fmaf(q0.z, k0.z, acc0);
                        acc0 = fmaf(q0.w, k0.w, acc0);
                    }
                }
                if (v0ok) {
                    float v = acc0 * scale;
                    Wl[wb + ci0] = (v > tau) ? (__expf(v) - 1.0f) : 0.0f;
                }
                if (v1ok) {
                    float v = acc1 * scale;
                    Wl[wb + ci1] = (v > tau) ? (__expf(v) - 1.0f) : 0.0f;
                }
            }
            __syncwarp();

            // scatter: list is row-grouped, so O index is compile-time
            #pragma unroll
            for (int j = 0; j < 8; j++) {
                int startj = (j == 0) ? 0 : __shfl_sync(0xffffffffu, pre, j * 4 - 1);
                int endj   = __shfl_sync(0xffffffffu, pre, j * 4 + 3);
                for (int t = startj; t < endj; t++) {
                    float w = Wl[wb + t];               // broadcast
                    int   c = Ls[wb + t] & 0xFFFF;      // broadcast
                    O[g * 8 + j][0] += w * Vs[c * FP + lane];
                    O[g * 8 + j][1] += w * Vs[c * FP + lane + 32];
                    dl[g * 8 + j] += w;
                }
            }
            __syncwarp();
        }
    }

    // ---- combine sumV partials --------------------------------------------
    __syncthreads();
    SVp[svg * 68 + svd] = sv;
    __syncthreads();
    float sv0 = 0.0f, sv1 = 0.0f;
    #pragma unroll
    for (int gg = 0; gg < 8; gg++) {
        sv0 += SVp[gg * 68 + lane];
        sv1 += SVp[gg * 68 + lane + 32];
    }

    // ---- finalize: rows owned by this warp --------------------------------
    const int b_ = bh >> 2, h = bh & 3;
    const int tbase = b_ * 4096 + qt * 256;
    #pragma unroll
    for (int i = 0; i < 16; i++) {
        float inv = 1.0f / (4096.0f + dl[i]);
        int t = tbase + R0 + i;
        g_A[t * 256 + h * 64 + lane]      = (sv0 + O[i][0]) * inv;
        g_A[t * 256 + h * 64 + lane + 32] = (sv1 + O[i][1]) * inv;
    }
}

// ---------------------------------------------------------------------------
// Output projection via FFMA2: out[t,c] = sum_d g_A[t,d]*o_w[c,d] + o_b[c]
// ---------------------------------------------------------------------------
__global__ __launch_bounds__(256) void oproj_kernel(
    const float* __restrict__ ow, const float* __restrict__ ob,
    float* __restrict__ out)
{
    __shared__ float AsT[64 * QP];     // [d][r]
    __shared__ float Ws[64 * PITCH];   // [c][d]

    const int tr = blockIdx.x * 64;
    const int tc = blockIdx.y * 64;
    const int tid  = threadIdx.x;
    const int warp = tid >> 5;
    const int lane = tid & 31;

    unsigned long long acc2[4][2];
    #pragma unroll
    for (int p = 0; p < 4; p++) { acc2[p][0] = 0ull; acc2[p][1] = 0ull; }

    for (int kb_ = 0; kb_ < 256; kb_ += 64) {
        const float4* X4 = (const float4*)(g_A + tr * 256 + kb_);
        const float4* W4 = (const float4*)(ow + tc * 256 + kb_);
        #pragma unroll
        for (int it = 0; it < 4; it++) {
            int idx = tid + it * 256;      // < 1024
            int r = idx >> 4, d4 = idx & 15;
            float4 v = X4[r * 64 + d4];
            AsT[(d4 * 4 + 0) * QP + r] = v.x;
            AsT[(d4 * 4 + 1) * QP + r] = v.y;
            AsT[(d4 * 4 + 2) * QP + r] = v.z;
            AsT[(d4 * 4 + 3) * QP + r] = v.w;
            float4 wv = W4[r * 64 + d4];
            float* p = &Ws[r * PITCH + d4 * 4];
            p[0] = wv.x; p[1] = wv.y; p[2] = wv.z; p[3] = wv.w;
        }
        __syncthreads();

        #pragma unroll 8
        for (int d = 0; d < 64; d++) {
            const float* arow = &AsT[d * QP + warp * 8];
            unsigned long long ra[4];
            #pragma unroll
            for (int p = 0; p < 4; p++)
                ra[p] = *(const unsigned long long*)(arow + 2 * p);
            unsigned long long bb[2];
            #pragma unroll
            for (int jc = 0; jc < 2; jc++) {
                float b = Ws[(lane + 32 * jc) * PITCH + d];
                bb[jc] = pack2(b, b);
            }
            #pragma unroll
            for (int p = 0; p < 4; p++) {
                fma2acc(acc2[p][0], ra[p], bb[0]);
                fma2acc(acc2[p][1], ra[p], bb[1]);
            }
        }
        __syncthreads();
    }

    #pragma unroll
    for (int p = 0; p < 4; p++) {
        #pragma unroll
        for (int jc = 0; jc < 2; jc++) {
            float2 v = unpack2(acc2[p][jc]);
            int c = tc + lane + 32 * jc;
            float bv = ob[c];
            int t0 = tr + warp * 8 + 2 * p;
            out[t0 * 256 + c]       = v.x + bv;
            out[(t0 + 1) * 256 + c] = v.y + bv;
        }
    }
}

// ---------------------------------------------------------------------------
extern "C" void kernel_launch(void* const* d_in, const int* in_sizes, int n_in,
                              void* d_out, int out_size)
{
    const float* x   = (const float*)d_in[0];
    const float* qw  = (const float*)d_in[1];
    const float* qb  = (const float*)d_in[2];
    const float* kw  = (const float*)d_in[3];
    const float* kb  = (const float*)d_in[4];
    const float* vw  = (const float*)d_in[5];
    const float* vb  = (const float*)d_in[6];
    const float* ow  = (const float*)d_in[7];
    const float* ob  = (const float*)d_in[8];
    const float* tau = (const float*)d_in[9];
    float* out = (float*)d_out;

    static bool attr_set = false;
    const int qkv_smem = (64 * QP2 + 64 * PITCH) * (int)sizeof(float);
    if (!attr_set) {
        cudaFuncSetAttribute(attn_kernel,
                             cudaFuncAttributeMaxDynamicSharedMemorySize,
                             SM_TOTAL);
        cudaFuncSetAttribute(qkv_kernel,
                             cudaFuncAttributeMaxDynamicSharedMemorySize,
                             qkv_smem);
        attr_set = true;
    }

    // QKV projections (FFMA2, 128-row tiles): 64 x 128 rows = 8192 = B*N
    dim3 gq(64, 4, 3);
    qkv_kernel<<<gq, 256, qkv_smem>>>(x, qw, qb, kw, kb, vw, vb);

    // K -> bf16 copy (coalesced)
    cvtk_kernel<<<(8 * 4096 * 64 / 2) / 512, 512>>>();

    // attention: HMMA filter + exact sparse recompute (R11 verbatim)
    dim3 ga(16, 8);
    attn_kernel<<<ga, 512, SM_TOTAL>>>(tau);

    // output projection (FFMA2)
    dim3 go(128, 4);
    oproj_kernel<<<go, 256>>>(ow, ob, out);
}